// round 8
// baseline (speedup 1.0000x reference)
#include <cuda_runtime.h>
#include <cuda_bf16.h>
#include <cstdint>

// ---------------------------------------------------------------------------
// RelativeMultiHeadAttn (Transformer-XL style) forward.
//
// qkv = x @ Wqkv via tcgen05 bf16 split-precision GEMM (K concat trick):
//   A2 = [Xhi | Xlo | Xhi]  (4096 x 3072 bf16, K-major)
//   B2 = [Whi | Whi | Wlo]^T (3072 x 3072 bf16, K-major)
//   qkv = A2 @ B2^T  accumulated fp32 in TMEM  ==  x@W up to ~2^-18 residual.
// tcgen05 body guarded for the sm_103a arch-specific pass; plain compute_103
// pass compiles an FFMA fallback GEMM.
//
// score: 128x128 tiles, 8x8/thread; band-product trick:
//   BD_shift[i,j] = (q_i + r_w) . R[:, L + j - i]
//   E_term[i,j]   = k_j . R[:, L + i - j]
// ---------------------------------------------------------------------------

namespace {
constexpr int BATCH = 8;
constexpr int NH    = 16;
constexpr int SEQ   = 512;
constexpr int DM    = 1024;
constexpr int HD    = 64;
constexpr int P2    = 2 * SEQ;      // 1024
constexpr int BH    = BATCH * NH;   // 128
constexpr int QKV_N = 3 * DM;       // 3072
constexpr int MROWS = BATCH * SEQ;  // 4096
constexpr int KTOT  = 3 * DM;       // 3072 (split-K concat)
constexpr int CH    = 64;           // K chunk (one SW128 atom column of bf16)
constexpr int NCH   = KTOT / CH;    // 48
}

// scratch (static device globals: allowed; no dynamic allocation)
__device__ float         g_qkv[(size_t)MROWS * QKV_N];    // 50 MB fp32
__device__ __nv_bfloat16 g_A2[(size_t)MROWS * KTOT];      // 25 MB
__device__ __nv_bfloat16 g_B2[(size_t)QKV_N * KTOT];      // 19 MB

// Feature gate: true only in the sm_103a (arch-specific) device pass.
#ifndef __CUDA_ARCH_SPECIFIC__
#define __CUDA_ARCH_SPECIFIC__ 0
#endif
#if !defined(__CUDA_ARCH__) || defined(__CUDA_ARCH_FEAT_SM103_ALL) || \
    (__CUDA_ARCH_SPECIFIC__ == 1030)
#define HAS_TCGEN05 1
#else
#define HAS_TCGEN05 0
#endif

// ===========================================================================
// minimal sm_103a PTX helpers
// ===========================================================================
__device__ __forceinline__ uint32_t smem_u32(const void* p) {
  uint32_t a;
  asm("{ .reg .u64 t; cvta.to.shared.u64 t, %1; cvt.u32.u64 %0, t; }"
      : "=r"(a) : "l"(p));
  return a;
}
#if HAS_TCGEN05
__device__ __forceinline__ uint32_t elect_one() {
  uint32_t pred;
  asm volatile("{\n\t.reg .pred p;\n\telect.sync _|p, 0xFFFFFFFF;\n\t"
               "selp.b32 %0, 1, 0, p;\n\t}" : "=r"(pred));
  return pred;
}
__device__ __forceinline__ void mbar_init(uint32_t mbar, uint32_t cnt) {
  asm volatile("mbarrier.init.shared.b64 [%0], %1;" :: "r"(mbar), "r"(cnt) : "memory");
}
__device__ __forceinline__ void mbar_wait(uint32_t mbar, uint32_t parity) {
  asm volatile(
      "{\n\t.reg .pred P;\n\t"
      "WL_%=:\n\t"
      "mbarrier.try_wait.parity.acquire.cta.shared::cta.b64 P, [%0], %1, 0x989680;\n\t"
      "@P bra.uni WD_%=;\n\t"
      "bra.uni WL_%=;\n\t"
      "WD_%=:\n\t}"
      :: "r"(mbar), "r"(parity) : "memory");
}
__device__ __forceinline__ void tmem_alloc(uint32_t smem_dst, uint32_t ncols) {
  asm volatile("tcgen05.alloc.cta_group::1.sync.aligned.shared::cta.b32 [%0], %1;"
               :: "r"(smem_dst), "r"(ncols) : "memory");
}
__device__ __forceinline__ void tmem_relinq() {
  asm volatile("tcgen05.relinquish_alloc_permit.cta_group::1.sync.aligned;");
}
__device__ __forceinline__ void tmem_dealloc(uint32_t tmem, uint32_t ncols) {
  asm volatile("tcgen05.dealloc.cta_group::1.sync.aligned.b32 %0, %1;"
               :: "r"(tmem), "r"(ncols));
}
__device__ __forceinline__ void tcommit(uint32_t mbar) {
  asm volatile(
      "tcgen05.commit.cta_group::1.mbarrier::arrive::one.shared::cluster.b64 [%0];"
      :: "r"(mbar) : "memory");
}
__device__ __forceinline__ void fence_async_shared() {
  asm volatile("fence.proxy.async.shared::cta;" ::: "memory");
}
__device__ __forceinline__ void tfence_after() {
  asm volatile("tcgen05.fence::after_thread_sync;" ::: "memory");
}
__device__ __forceinline__ void mma_f16_ss(uint32_t d, uint64_t ad, uint64_t bd,
                                           uint32_t idesc, uint32_t en) {
  asm volatile(
      "{\n\t.reg .pred p;\n\tsetp.ne.u32 p, %5, 0;\n\t"
      "tcgen05.mma.cta_group::1.kind::f16 [%0], %1, %2, %3, {%4, %4, %4, %4}, p;\n\t}"
      :: "r"(d), "l"(ad), "l"(bd), "r"(idesc), "r"(0u), "r"(en) : "memory");
}
#define TC_LD_X32(r, addr)                                                      \
  asm volatile(                                                                 \
      "tcgen05.ld.sync.aligned.32x32b.x32.b32 "                                 \
      "{%0,%1,%2,%3,%4,%5,%6,%7,%8,%9,%10,%11,%12,%13,%14,%15,"                \
      "%16,%17,%18,%19,%20,%21,%22,%23,%24,%25,%26,%27,%28,%29,%30,%31}, [%32];" \
      : "=r"((r)[0]), "=r"((r)[1]), "=r"((r)[2]), "=r"((r)[3]),                 \
        "=r"((r)[4]), "=r"((r)[5]), "=r"((r)[6]), "=r"((r)[7]),                 \
        "=r"((r)[8]), "=r"((r)[9]), "=r"((r)[10]), "=r"((r)[11]),               \
        "=r"((r)[12]), "=r"((r)[13]), "=r"((r)[14]), "=r"((r)[15]),             \
        "=r"((r)[16]), "=r"((r)[17]), "=r"((r)[18]), "=r"((r)[19]),             \
        "=r"((r)[20]), "=r"((r)[21]), "=r"((r)[22]), "=r"((r)[23]),             \
        "=r"((r)[24]), "=r"((r)[25]), "=r"((r)[26]), "=r"((r)[27]),             \
        "=r"((r)[28]), "=r"((r)[29]), "=r"((r)[30]), "=r"((r)[31])              \
      : "r"(addr))
__device__ __forceinline__ void tc_wait_ld() {
  asm volatile("tcgen05.wait::ld.sync.aligned;" ::: "memory");
}
// SW128 K-major SMEM descriptor (LBO=1, SBO=64, version=1, layout=2)
__device__ __forceinline__ uint64_t smem_desc_sw128(uint32_t addr) {
  const uint64_t base = (uint64_t(2) << 61) | (uint64_t(1) << 46) |
                        (uint64_t(64) << 32) | (uint64_t(1) << 16);
  return base | ((uint64_t)(addr >> 4) & 0x3FFF);
}
#endif  // HAS_TCGEN05

// idesc: fp32 accum, bf16 x bf16, M=128, N=128
namespace {
constexpr uint32_t IDESC =
    (1u << 4) | (1u << 7) | (1u << 10) | ((128u / 8) << 17) | ((128u / 16) << 24);
}

// ===========================================================================
// Conversion kernels: fp32 -> split bf16 (hi/lo), B transposed to K-major
// ===========================================================================
__global__ __launch_bounds__(256) void k_convA(const float* __restrict__ X) {
  size_t i = (size_t)blockIdx.x * 256 + threadIdx.x;  // quad index
  float4 v = ((const float4*)X)[i];
  size_t m = i >> 8;
  size_t q = (i & 255) * 4;

  __nv_bfloat162 h01 = __floats2bfloat162_rn(v.x, v.y);
  __nv_bfloat162 h23 = __floats2bfloat162_rn(v.z, v.w);
  float lx = v.x - __bfloat162float(h01.x);
  float ly = v.y - __bfloat162float(h01.y);
  float lz = v.z - __bfloat162float(h23.x);
  float lw = v.w - __bfloat162float(h23.y);
  __nv_bfloat162 l01 = __floats2bfloat162_rn(lx, ly);
  __nv_bfloat162 l23 = __floats2bfloat162_rn(lz, lw);

  uint2 uh, ul;
  uh.x = *(uint32_t*)&h01; uh.y = *(uint32_t*)&h23;
  ul.x = *(uint32_t*)&l01; ul.y = *(uint32_t*)&l23;

  __nv_bfloat16* row = g_A2 + m * KTOT;
  *(uint2*)(row + q)          = uh;
  *(uint2*)(row + DM + q)     = ul;
  *(uint2*)(row + 2 * DM + q) = uh;
}

__global__ __launch_bounds__(256) void k_convB(const float* __restrict__ W) {
  __shared__ float tile[32][33];
  const int n0 = blockIdx.x * 32;
  const int k0 = blockIdx.y * 32;
  const int tid = threadIdx.x;
#pragma unroll
  for (int it = 0; it < 4; it++) {
    int e = tid + it * 256;
    int kk = e >> 5, nn = e & 31;
    tile[kk][nn] = W[(size_t)(k0 + kk) * QKV_N + n0 + nn];
  }
  __syncthreads();
#pragma unroll
  for (int it = 0; it < 4; it++) {
    int e = tid + it * 256;
    int nn = e >> 5, kk = e & 31;
    float x = tile[kk][nn];
    __nv_bfloat16 hi = __float2bfloat16_rn(x);
    __nv_bfloat16 lo = __float2bfloat16_rn(x - __bfloat162float(hi));
    __nv_bfloat16* row = g_B2 + (size_t)(n0 + nn) * KTOT;
    row[k0 + kk]          = hi;
    row[DM + k0 + kk]     = hi;
    row[2 * DM + k0 + kk] = lo;
  }
}

// ===========================================================================
// Kernel: qkv = A2 @ B2^T via tcgen05 (unchanged from round 7)
// ===========================================================================
namespace {
constexpr int QSMEM = 1024 + 4 * 16384;
}

__global__ __launch_bounds__(256) void k_qkv_mma(const float* __restrict__ X,
                                                 const float* __restrict__ W) {
#if HAS_TCGEN05
  extern __shared__ char smem[];
  const uint32_t sb = smem_u32(smem);
  const uint32_t TPTR  = sb;
  const uint32_t MBAR0 = sb + 16;
  const uint32_t MBAR1 = sb + 24;
  const uint32_t STAGE = sb + 1024;

  const int tid = threadIdx.x;
  const int wid = tid >> 5;

  if (wid == 0) tmem_alloc(TPTR, 128);
  if (tid == 0) { mbar_init(MBAR0, 1); mbar_init(MBAR1, 1); }
  __syncthreads();
  uint32_t tmem;
  asm volatile("ld.shared.b32 %0, [%1];" : "=r"(tmem) : "r"(TPTR));
  if (wid == 0) tmem_relinq();

  const int m0 = blockIdx.y * 128;
  const int n0 = blockIdx.x * 128;
  const __nv_bfloat16* Ag = g_A2 + (size_t)m0 * KTOT;
  const __nv_bfloat16* Bg = g_B2 + (size_t)n0 * KTOT;

  const int row = tid >> 1;
  const int sg0 = (tid & 1) * 4;

  uint32_t ph0 = 0, ph1 = 0;
  for (int t = 0; t < NCH; t++) {
    const int p = t & 1;
    const uint32_t Abase = STAGE + p * 32768;
    const uint32_t Bbase = Abase + 16384;
    if (t >= 2) {
      if (p == 0) { mbar_wait(MBAR0, ph0); ph0 ^= 1; }
      else        { mbar_wait(MBAR1, ph1); ph1 ^= 1; }
    }
    const int kc = t * CH;
    uint4 av[4], bv[4];
    const char* arow = (const char*)(Ag + (size_t)row * KTOT + kc);
    const char* brow = (const char*)(Bg + (size_t)row * KTOT + kc);
#pragma unroll
    for (int s = 0; s < 4; s++) {
      av[s] = *(const uint4*)(arow + (sg0 + s) * 16);
      bv[s] = *(const uint4*)(brow + (sg0 + s) * 16);
    }
#pragma unroll
    for (int s = 0; s < 4; s++) {
      uint32_t off = row * 128 + (sg0 + s) * 16;
      uint32_t sw = off ^ ((off >> 3) & 0x70);
      *(uint4*)(smem + (Abase - sb) + sw) = av[s];
      *(uint4*)(smem + (Bbase - sb) + sw) = bv[s];
    }
    __syncthreads();
    if (wid == 0) {
      if (elect_one()) {
        fence_async_shared();
        uint64_t ad = smem_desc_sw128(Abase);
        uint64_t bd = smem_desc_sw128(Bbase);
#pragma unroll
        for (int k = 0; k < 4; k++)
          mma_f16_ss(tmem, ad + k * 2, bd + k * 2, IDESC, (t > 0 || k > 0) ? 1u : 0u);
        tcommit(p == 0 ? MBAR0 : MBAR1);
      }
    }
  }
  mbar_wait(MBAR1, ph1);
  tfence_after();

  if (wid < 4) {
    const int lid = tid & 31;
    const int orow = m0 + wid * 32 + lid;
#pragma unroll
    for (int cb = 0; cb < 128; cb += 32) {
      uint32_t d[32];
      TC_LD_X32(d, tmem + cb);
      tc_wait_ld();
      float* dst = g_qkv + (size_t)orow * QKV_N + n0 + cb;
#pragma unroll
      for (int c = 0; c < 32; c += 4)
        *(float4*)(dst + c) = make_float4(__uint_as_float(d[c]),
                                          __uint_as_float(d[c + 1]),
                                          __uint_as_float(d[c + 2]),
                                          __uint_as_float(d[c + 3]));
    }
  }
  __syncthreads();
  if (wid == 0) tmem_dealloc(tmem, 128);

#else  // ------------- FFMA fallback (non-sm_103a pass; still correct) -------
  extern __shared__ char smemraw[];
  float* sA = (float*)smemraw;
  float* sB = sA + 16 * 128;
  const int K = DM, N = QKV_N;
  const int tid = threadIdx.x;
  const int tx = tid & 15, ty = tid >> 4;
  const int row0 = blockIdx.y * 128;
  const int col0 = blockIdx.x * 128;

  float acc[8][8];
#pragma unroll
  for (int r = 0; r < 8; r++)
#pragma unroll
    for (int c = 0; c < 8; c++) acc[r][c] = 0.f;

  for (int kk = 0; kk < K; kk += 16) {
#pragma unroll
    for (int it = 0; it < 2; it++) {
      int e = tid + it * 256;
      int ar = e >> 2;
      int ac = (e & 3) * 4;
      float4 a4 = *(const float4*)(X + (size_t)(row0 + ar) * K + kk + ac);
      sA[(ac + 0) * 128 + ar] = a4.x;
      sA[(ac + 1) * 128 + ar] = a4.y;
      sA[(ac + 2) * 128 + ar] = a4.z;
      sA[(ac + 3) * 128 + ar] = a4.w;
    }
#pragma unroll
    for (int it = 0; it < 2; it++) {
      int e = tid + it * 256;
      int br = e >> 5;
      int bc = (e & 31) * 4;
      *(float4*)&sB[br * 128 + bc] = *(const float4*)(W + (size_t)(kk + br) * N + col0 + bc);
    }
    __syncthreads();
#pragma unroll
    for (int k = 0; k < 16; k++) {
      float ar[8], bc[8];
      *(float4*)&ar[0] = *(float4*)&sA[k * 128 + ty * 8];
      *(float4*)&ar[4] = *(float4*)&sA[k * 128 + ty * 8 + 4];
      *(float4*)&bc[0] = *(float4*)&sB[k * 128 + tx * 8];
      *(float4*)&bc[4] = *(float4*)&sB[k * 128 + tx * 8 + 4];
#pragma unroll
      for (int r = 0; r < 8; r++)
#pragma unroll
        for (int c = 0; c < 8; c++) acc[r][c] += ar[r] * bc[c];
    }
    __syncthreads();
  }
#pragma unroll
  for (int r = 0; r < 8; r++) {
    float* dst = g_qkv + (size_t)(row0 + ty * 8 + r) * QKV_N + col0 + tx * 8;
    *(float4*)dst       = make_float4(acc[r][0], acc[r][1], acc[r][2], acc[r][3]);
    *(float4*)(dst + 4) = make_float4(acc[r][4], acc[r][5], acc[r][6], acc[r][7]);
  }
#endif
}

// ===========================================================================
// Kernel: fused score. 128x128 tile, 256 threads, strided 8x8 per thread.
// attn_score = (AC + BD + E)/8 + prev -> prev_out
// ===========================================================================
namespace {
constexpr int SC_SMEM = (64 * 128 * 2 + 64 * 256 * 2) * 4;  // 196608 B
}

__global__ __launch_bounds__(256) void k_score(const float* __restrict__ rrb,
                                               const float* __restrict__ rwb,
                                               const float* __restrict__ relpos,
                                               const float* __restrict__ prev,
                                               const int* __restrict__ skip,
                                               float* __restrict__ prev_out) {
  extern __shared__ float smemf[];
  float* sQT = smemf;                  // [64][128]  d-major
  float* sKT = sQT + 64 * 128;         // [64][128]
  float* sRq = sKT + 64 * 128;         // [64][256]  band for BD (255 used)
  float* sRe = sRq + 64 * 256;         // [64][256]  band for E
  __shared__ float cK[128];            // rrb . k_j
  __shared__ float cRq[256];           // rwb . R_t  (255 used)

  const int bh = blockIdx.z;
  const int b = bh >> 4, h = bh & 15;
  const int tid = threadIdx.x;
  const int tx = tid & 15, ty = tid >> 4;
  const int i0 = blockIdx.y * 128;
  const int j0 = blockIdx.x * 128;

  const float* Qb = g_qkv + (size_t)(b * SEQ) * QKV_N + h * HD;
  const float* Kb = Qb + DM;

  // load q/k tiles transposed (d-major). lanes map to consecutive rows ->
  // conflict-free stores at stride 128.
#pragma unroll
  for (int it = 0; it < 8; it++) {
    int e = tid + it * 256;       // 0..2047
    int r = e & 127;
    int c = (e >> 7) * 4;         // 0,4,...,60
    float4 q4 = *(const float4*)(Qb + (size_t)(i0 + r) * QKV_N + c);
    sQT[(c + 0) * 128 + r] = q4.x;
    sQT[(c + 1) * 128 + r] = q4.y;
    sQT[(c + 2) * 128 + r] = q4.z;
    sQT[(c + 3) * 128 + r] = q4.w;
    float4 k4 = *(const float4*)(Kb + (size_t)(j0 + r) * QKV_N + c);
    sKT[(c + 0) * 128 + r] = k4.x;
    sKT[(c + 1) * 128 + r] = k4.y;
    sKT[(c + 2) * 128 + r] = k4.z;
    sKT[(c + 3) * 128 + r] = k4.w;
  }
  // R bands: global cols [q0, q0+254] and [u0, u0+254]; always within [1,1023]
  {
    const int q0 = SEQ + (j0 - i0) - 127;
    const int u0 = SEQ + (i0 - j0) - 127;
    for (int e = tid; e < 64 * 255; e += 256) {
      int d = e / 255, x = e - d * 255;
      sRq[d * 256 + x] = relpos[(size_t)d * P2 + q0 + x];
      sRe[d * 256 + x] = relpos[(size_t)d * P2 + u0 + x];
    }
  }
  __syncthreads();

  // rank-1 bias corrections
  if (tid < 128) {
    float s = 0.f;
#pragma unroll
    for (int d = 0; d < 64; d++) s += rrb[h * HD + d] * sKT[d * 128 + tid];
    cK[tid] = s;
  }
  if (tid < 255) {
    float s = 0.f;
#pragma unroll
    for (int d = 0; d < 64; d++) s += rwb[h * HD + d] * sRq[d * 256 + tid];
    cRq[tid] = s;
  }
  __syncthreads();

  float acc[8][8];
#pragma unroll
  for (int r = 0; r < 8; r++)
#pragma unroll
    for (int c = 0; c < 8; c++) acc[r][c] = 0.f;

  const int bq = tx - ty + 15;   // rq band base (idx = bq + 16m, m=c-r+7)
  const int be = ty - tx + 15;   // re band base (idx = be + 16m, m=r-c+7)

#pragma unroll 2
  for (int d = 0; d < 64; d++) {
    float a[8], bb[8], rq[15], re[15];
#pragma unroll
    for (int r = 0; r < 8; r++) a[r]  = sQT[d * 128 + ty + 16 * r];
#pragma unroll
    for (int c = 0; c < 8; c++) bb[c] = sKT[d * 128 + tx + 16 * c];
#pragma unroll
    for (int m = 0; m < 15; m++) rq[m] = sRq[d * 256 + bq + 16 * m];
#pragma unroll
    for (int m = 0; m < 15; m++) re[m] = sRe[d * 256 + be + 16 * m];
#pragma unroll
    for (int r = 0; r < 8; r++)
#pragma unroll
      for (int c = 0; c < 8; c++)
        acc[r][c] += a[r] * bb[c] + a[r] * rq[c - r + 7] + bb[c] * re[r - c + 7];
  }

  const int sk = *skip;
  const float* prevb = prev + (size_t)bh * SEQ * SEQ;
  float* outb = prev_out + (size_t)bh * SEQ * SEQ;

#pragma unroll
  for (int r = 0; r < 8; r++) {
    int i = i0 + ty + 16 * r;
#pragma unroll
    for (int c = 0; c < 8; c++) {
      int j = j0 + tx + 16 * c;
      float s = acc[r][c] + cK[tx + 16 * c]
              + cRq[(tx + 16 * c) - (ty + 16 * r) + 127];
      s *= 0.125f;   // 1/sqrt(64)
      if (sk) s += prevb[(size_t)i * SEQ + j];
      outb[(size_t)i * SEQ + j] = s;
    }
  }
}

// ===========================================================================
// Kernel: out = softmax(S) @ V. 64 rows/block, 4x4 tile, PV loop pipelined.
// ===========================================================================
namespace {
constexpr int ROWS_AV   = 64;
constexpr int SS_STRIDE = 516;
constexpr int SMEM_AV   = (ROWS_AV * SS_STRIDE + 64 * 64) * 4;  // 148480 B
}

__global__ __launch_bounds__(256) void k_av(const float* __restrict__ Sglob,
                                            float* __restrict__ Out) {
  extern __shared__ float smemf[];
  float* sS = smemf;
  float* sV = smemf + ROWS_AV * SS_STRIDE;
  __shared__ float sSum[ROWS_AV];

  const int bh = blockIdx.y;
  const int b = bh >> 4, h = bh & 15;
  const int row0 = blockIdx.x * ROWS_AV;
  const int tid = threadIdx.x;
  const int tx = tid & 15, ty = tid >> 4;
  const float* Sb = Sglob + ((size_t)bh * SEQ + row0) * SEQ;

#pragma unroll
  for (int it = 0; it < 32; it++) {
    int e = tid + it * 256;
    int r = e >> 7;
    int c = (e & 127) * 4;
    *(float4*)&sS[r * SS_STRIDE + c] = *(const float4*)(Sb + (size_t)r * SEQ + c);
  }
  __syncthreads();

  {
    const int warp = tid >> 5, lane = tid & 31;
#pragma unroll
    for (int rr = 0; rr < 8; rr++) {
      int row = warp * 8 + rr;
      float* srow = sS + row * SS_STRIDE;
      float mx = -1e30f;
      for (int c = lane; c < SEQ; c += 32) mx = fmaxf(mx, srow[c]);
#pragma unroll
      for (int o = 16; o > 0; o >>= 1) mx = fmaxf(mx, __shfl_xor_sync(0xffffffffu, mx, o));
      float sum = 0.f;
      for (int c = lane; c < SEQ; c += 32) {
        float p = __expf(srow[c] - mx);
        srow[c] = p;
        sum += p;
      }
#pragma unroll
      for (int o = 16; o > 0; o >>= 1) sum += __shfl_xor_sync(0xffffffffu, sum, o);
      if (lane == 0) sSum[row] = sum;
    }
  }

  float acc[4][4];
#pragma unroll
  for (int r = 0; r < 4; r++)
#pragma unroll
    for (int c = 0; c < 4; c++) acc[r][c] = 0.f;

  const float* Vb = g_qkv + (size_t)(b * SEQ) * QKV_N + 2 * DM + h * HD;
  for (int kc = 0; kc < SEQ; kc += 64) {
    __syncthreads();
#pragma unroll
    for (int it = 0; it < 4; it++) {
      int e = tid + it * 256;
      int kk = e >> 4;
      int c = (e & 15) * 4;
      *(float4*)&sV[kk * 64 + c] = *(const float4*)(Vb + (size_t)(kc + kk) * QKV_N + c);
    }
    __syncthreads();

    // software-pipelined PV: preload kk+1 while computing kk
    float pc[4], vc[4], pn[4], vn[4];
#pragma unroll
    for (int r = 0; r < 4; r++) pc[r] = sS[(ty + 16 * r) * SS_STRIDE + kc];
#pragma unroll
    for (int c = 0; c < 4; c++) vc[c] = sV[tx + 16 * c];
#pragma unroll 7
    for (int kk = 0; kk < 63; kk++) {
#pragma unroll
      for (int r = 0; r < 4; r++) pn[r] = sS[(ty + 16 * r) * SS_STRIDE + kc + kk + 1];
#pragma unroll
      for (int c = 0; c < 4; c++) vn[c] = sV[(kk + 1) * 64 + tx + 16 * c];
#pragma unroll
      for (int r = 0; r < 4; r++)
#pragma unroll
        for (int c = 0; c < 4; c++) acc[r][c] += pc[r] * vc[c];
#pragma unroll
      for (int r = 0; r < 4; r++) pc[r] = pn[r];
#pragma unroll
      for (int c = 0; c < 4; c++) vc[c] = vn[c];
    }
#pragma unroll
    for (int r = 0; r < 4; r++)
#pragma unroll
      for (int c = 0; c < 4; c++) acc[r][c] += pc[r] * vc[c];
  }

#pragma unroll
  for (int r = 0; r < 4; r++) {
    const float inv = 1.f / sSum[ty + 16 * r];
    float* dst = Out + ((size_t)b * SEQ + row0 + ty + 16 * r) * DM + h * HD + tx;
#pragma unroll
    for (int c = 0; c < 4; c++) dst[16 * c] = acc[r][c] * inv;
  }
}

// ---------------------------------------------------------------------------
extern "C" void kernel_launch(void* const* d_in, const int* in_sizes, int n_in,
                              void* d_out, int out_size) {
  const float* x      = (const float*)d_in[0];
  const float* prev   = (const float*)d_in[1];
  const float* Wqkv   = (const float*)d_in[2];
  const float* rrb    = (const float*)d_in[3];
  const float* rwb    = (const float*)d_in[4];
  const float* relpos = (const float*)d_in[5];
  const int*   skip   = (const int*)d_in[6];

  float* out      = (float*)d_out;                       // (8,512,1024)
  float* prev_out = out + (size_t)BATCH * SEQ * DM;      // (8,16,512,512)

  k_convA<<<(MROWS * DM / 4) / 256, 256>>>(x);
  k_convB<<<dim3(QKV_N / 32, DM / 32), 256>>>(Wqkv);

  cudaFuncSetAttribute(k_qkv_mma, cudaFuncAttributeMaxDynamicSharedMemorySize, QSMEM);
  k_qkv_mma<<<dim3(QKV_N / 128, MROWS / 128), 256, QSMEM>>>(x, Wqkv);

  cudaFuncSetAttribute(k_score, cudaFuncAttributeMaxDynamicSharedMemorySize, SC_SMEM);
  dim3 g3(SEQ / 128, SEQ / 128, BH);                     // (4, 4, 128)
  k_score<<<g3, 256, SC_SMEM>>>(rrb, rwb, relpos, prev, skip, prev_out);

  cudaFuncSetAttribute(k_av, cudaFuncAttributeMaxDynamicSharedMemorySize, SMEM_AV);
  dim3 g4(SEQ / ROWS_AV, BH);                            // (8, 128)
  k_av<<<g4, 256, SMEM_AV>>>(prev_out, out);
}

// round 9
// speedup vs baseline: 1.5591x; 1.5591x over previous
#include <cuda_runtime.h>
#include <cuda_bf16.h>
#include <cstdint>

// ---------------------------------------------------------------------------
// RelativeMultiHeadAttn (Transformer-XL style) forward.
//
// qkv = x @ Wqkv via tcgen05 bf16 split-precision GEMM (K concat trick):
//   A2 = [Xhi | Xlo | Xhi]  (4096 x 3072 bf16, K-major)
//   B2 = [Whi | Whi | Wlo]^T (3072 x 3072 bf16, K-major)
//   qkv = A2 @ B2^T  accumulated fp32 in TMEM  ==  x@W up to ~2^-18 residual.
// tcgen05 body guarded for the sm_103a arch-specific pass; plain compute_103
// pass compiles an FFMA fallback GEMM.
//
// score: 64x64 tiles, blocked 4x4/thread with LDS.128; band-product trick:
//   BD_shift[i,j] = (q_i + r_w) . R[:, L + j - i]
//   E_term[i,j]   = k_j . R[:, L + i - j]
// ---------------------------------------------------------------------------

namespace {
constexpr int BATCH = 8;
constexpr int NH    = 16;
constexpr int SEQ   = 512;
constexpr int DM    = 1024;
constexpr int HD    = 64;
constexpr int P2    = 2 * SEQ;      // 1024
constexpr int BH    = BATCH * NH;   // 128
constexpr int QKV_N = 3 * DM;       // 3072
constexpr int MROWS = BATCH * SEQ;  // 4096
constexpr int KTOT  = 3 * DM;       // 3072 (split-K concat)
constexpr int CH    = 64;           // K chunk (one SW128 atom column of bf16)
constexpr int NCH   = KTOT / CH;    // 48
}

// scratch (static device globals: allowed; no dynamic allocation)
__device__ float         g_qkv[(size_t)MROWS * QKV_N];    // 50 MB fp32
__device__ __nv_bfloat16 g_A2[(size_t)MROWS * KTOT];      // 25 MB
__device__ __nv_bfloat16 g_B2[(size_t)QKV_N * KTOT];      // 19 MB

// Feature gate: true only in the sm_103a (arch-specific) device pass.
#ifndef __CUDA_ARCH_SPECIFIC__
#define __CUDA_ARCH_SPECIFIC__ 0
#endif
#if !defined(__CUDA_ARCH__) || defined(__CUDA_ARCH_FEAT_SM103_ALL) || \
    (__CUDA_ARCH_SPECIFIC__ == 1030)
#define HAS_TCGEN05 1
#else
#define HAS_TCGEN05 0
#endif

// ===========================================================================
// minimal sm_103a PTX helpers
// ===========================================================================
__device__ __forceinline__ uint32_t smem_u32(const void* p) {
  uint32_t a;
  asm("{ .reg .u64 t; cvta.to.shared.u64 t, %1; cvt.u32.u64 %0, t; }"
      : "=r"(a) : "l"(p));
  return a;
}
#if HAS_TCGEN05
__device__ __forceinline__ uint32_t elect_one() {
  uint32_t pred;
  asm volatile("{\n\t.reg .pred p;\n\telect.sync _|p, 0xFFFFFFFF;\n\t"
               "selp.b32 %0, 1, 0, p;\n\t}" : "=r"(pred));
  return pred;
}
__device__ __forceinline__ void mbar_init(uint32_t mbar, uint32_t cnt) {
  asm volatile("mbarrier.init.shared.b64 [%0], %1;" :: "r"(mbar), "r"(cnt) : "memory");
}
__device__ __forceinline__ void mbar_wait(uint32_t mbar, uint32_t parity) {
  asm volatile(
      "{\n\t.reg .pred P;\n\t"
      "WL_%=:\n\t"
      "mbarrier.try_wait.parity.acquire.cta.shared::cta.b64 P, [%0], %1, 0x989680;\n\t"
      "@P bra.uni WD_%=;\n\t"
      "bra.uni WL_%=;\n\t"
      "WD_%=:\n\t}"
      :: "r"(mbar), "r"(parity) : "memory");
}
__device__ __forceinline__ void tmem_alloc(uint32_t smem_dst, uint32_t ncols) {
  asm volatile("tcgen05.alloc.cta_group::1.sync.aligned.shared::cta.b32 [%0], %1;"
               :: "r"(smem_dst), "r"(ncols) : "memory");
}
__device__ __forceinline__ void tmem_relinq() {
  asm volatile("tcgen05.relinquish_alloc_permit.cta_group::1.sync.aligned;");
}
__device__ __forceinline__ void tmem_dealloc(uint32_t tmem, uint32_t ncols) {
  asm volatile("tcgen05.dealloc.cta_group::1.sync.aligned.b32 %0, %1;"
               :: "r"(tmem), "r"(ncols));
}
__device__ __forceinline__ void tcommit(uint32_t mbar) {
  asm volatile(
      "tcgen05.commit.cta_group::1.mbarrier::arrive::one.shared::cluster.b64 [%0];"
      :: "r"(mbar) : "memory");
}
__device__ __forceinline__ void fence_async_shared() {
  asm volatile("fence.proxy.async.shared::cta;" ::: "memory");
}
__device__ __forceinline__ void tfence_after() {
  asm volatile("tcgen05.fence::after_thread_sync;" ::: "memory");
}
__device__ __forceinline__ void mma_f16_ss(uint32_t d, uint64_t ad, uint64_t bd,
                                           uint32_t idesc, uint32_t en) {
  asm volatile(
      "{\n\t.reg .pred p;\n\tsetp.ne.u32 p, %5, 0;\n\t"
      "tcgen05.mma.cta_group::1.kind::f16 [%0], %1, %2, %3, {%4, %4, %4, %4}, p;\n\t}"
      :: "r"(d), "l"(ad), "l"(bd), "r"(idesc), "r"(0u), "r"(en) : "memory");
}
#define TC_LD_X32(r, addr)                                                      \
  asm volatile(                                                                 \
      "tcgen05.ld.sync.aligned.32x32b.x32.b32 "                                 \
      "{%0,%1,%2,%3,%4,%5,%6,%7,%8,%9,%10,%11,%12,%13,%14,%15,"                \
      "%16,%17,%18,%19,%20,%21,%22,%23,%24,%25,%26,%27,%28,%29,%30,%31}, [%32];" \
      : "=r"((r)[0]), "=r"((r)[1]), "=r"((r)[2]), "=r"((r)[3]),                 \
        "=r"((r)[4]), "=r"((r)[5]), "=r"((r)[6]), "=r"((r)[7]),                 \
        "=r"((r)[8]), "=r"((r)[9]), "=r"((r)[10]), "=r"((r)[11]),               \
        "=r"((r)[12]), "=r"((r)[13]), "=r"((r)[14]), "=r"((r)[15]),             \
        "=r"((r)[16]), "=r"((r)[17]), "=r"((r)[18]), "=r"((r)[19]),             \
        "=r"((r)[20]), "=r"((r)[21]), "=r"((r)[22]), "=r"((r)[23]),             \
        "=r"((r)[24]), "=r"((r)[25]), "=r"((r)[26]), "=r"((r)[27]),             \
        "=r"((r)[28]), "=r"((r)[29]), "=r"((r)[30]), "=r"((r)[31])              \
      : "r"(addr))
__device__ __forceinline__ void tc_wait_ld() {
  asm volatile("tcgen05.wait::ld.sync.aligned;" ::: "memory");
}
// SW128 K-major SMEM descriptor (LBO=1, SBO=64, version=1, layout=2)
__device__ __forceinline__ uint64_t smem_desc_sw128(uint32_t addr) {
  const uint64_t base = (uint64_t(2) << 61) | (uint64_t(1) << 46) |
                        (uint64_t(64) << 32) | (uint64_t(1) << 16);
  return base | ((uint64_t)(addr >> 4) & 0x3FFF);
}
#endif  // HAS_TCGEN05

// idesc: fp32 accum, bf16 x bf16, M=128, N=128
namespace {
constexpr uint32_t IDESC =
    (1u << 4) | (1u << 7) | (1u << 10) | ((128u / 8) << 17) | ((128u / 16) << 24);
}

// ===========================================================================
// Conversion kernels: fp32 -> split bf16 (hi/lo), B transposed to K-major
// ===========================================================================
__global__ __launch_bounds__(256) void k_convA(const float* __restrict__ X) {
  size_t i = (size_t)blockIdx.x * 256 + threadIdx.x;  // quad index
  float4 v = ((const float4*)X)[i];
  size_t m = i >> 8;
  size_t q = (i & 255) * 4;

  __nv_bfloat162 h01 = __floats2bfloat162_rn(v.x, v.y);
  __nv_bfloat162 h23 = __floats2bfloat162_rn(v.z, v.w);
  float lx = v.x - __bfloat162float(h01.x);
  float ly = v.y - __bfloat162float(h01.y);
  float lz = v.z - __bfloat162float(h23.x);
  float lw = v.w - __bfloat162float(h23.y);
  __nv_bfloat162 l01 = __floats2bfloat162_rn(lx, ly);
  __nv_bfloat162 l23 = __floats2bfloat162_rn(lz, lw);

  uint2 uh, ul;
  uh.x = *(uint32_t*)&h01; uh.y = *(uint32_t*)&h23;
  ul.x = *(uint32_t*)&l01; ul.y = *(uint32_t*)&l23;

  __nv_bfloat16* row = g_A2 + m * KTOT;
  *(uint2*)(row + q)          = uh;
  *(uint2*)(row + DM + q)     = ul;
  *(uint2*)(row + 2 * DM + q) = uh;
}

__global__ __launch_bounds__(256) void k_convB(const float* __restrict__ W) {
  __shared__ float tile[32][33];
  const int n0 = blockIdx.x * 32;
  const int k0 = blockIdx.y * 32;
  const int tid = threadIdx.x;
#pragma unroll
  for (int it = 0; it < 4; it++) {
    int e = tid + it * 256;
    int kk = e >> 5, nn = e & 31;
    tile[kk][nn] = W[(size_t)(k0 + kk) * QKV_N + n0 + nn];
  }
  __syncthreads();
#pragma unroll
  for (int it = 0; it < 4; it++) {
    int e = tid + it * 256;
    int nn = e >> 5, kk = e & 31;
    float x = tile[kk][nn];
    __nv_bfloat16 hi = __float2bfloat16_rn(x);
    __nv_bfloat16 lo = __float2bfloat16_rn(x - __bfloat162float(hi));
    __nv_bfloat16* row = g_B2 + (size_t)(n0 + nn) * KTOT;
    row[k0 + kk]          = hi;
    row[DM + k0 + kk]     = hi;
    row[2 * DM + k0 + kk] = lo;
  }
}

// ===========================================================================
// Kernel: qkv = A2 @ B2^T via tcgen05 (unchanged from round 7)
// ===========================================================================
namespace {
constexpr int QSMEM = 1024 + 4 * 16384;
}

__global__ __launch_bounds__(256) void k_qkv_mma(const float* __restrict__ X,
                                                 const float* __restrict__ W) {
#if HAS_TCGEN05
  extern __shared__ char smem[];
  const uint32_t sb = smem_u32(smem);
  const uint32_t TPTR  = sb;
  const uint32_t MBAR0 = sb + 16;
  const uint32_t MBAR1 = sb + 24;
  const uint32_t STAGE = sb + 1024;

  const int tid = threadIdx.x;
  const int wid = tid >> 5;

  if (wid == 0) tmem_alloc(TPTR, 128);
  if (tid == 0) { mbar_init(MBAR0, 1); mbar_init(MBAR1, 1); }
  __syncthreads();
  uint32_t tmem;
  asm volatile("ld.shared.b32 %0, [%1];" : "=r"(tmem) : "r"(TPTR));
  if (wid == 0) tmem_relinq();

  const int m0 = blockIdx.y * 128;
  const int n0 = blockIdx.x * 128;
  const __nv_bfloat16* Ag = g_A2 + (size_t)m0 * KTOT;
  const __nv_bfloat16* Bg = g_B2 + (size_t)n0 * KTOT;

  const int row = tid >> 1;
  const int sg0 = (tid & 1) * 4;

  uint32_t ph0 = 0, ph1 = 0;
  for (int t = 0; t < NCH; t++) {
    const int p = t & 1;
    const uint32_t Abase = STAGE + p * 32768;
    const uint32_t Bbase = Abase + 16384;
    if (t >= 2) {
      if (p == 0) { mbar_wait(MBAR0, ph0); ph0 ^= 1; }
      else        { mbar_wait(MBAR1, ph1); ph1 ^= 1; }
    }
    const int kc = t * CH;
    uint4 av[4], bv[4];
    const char* arow = (const char*)(Ag + (size_t)row * KTOT + kc);
    const char* brow = (const char*)(Bg + (size_t)row * KTOT + kc);
#pragma unroll
    for (int s = 0; s < 4; s++) {
      av[s] = *(const uint4*)(arow + (sg0 + s) * 16);
      bv[s] = *(const uint4*)(brow + (sg0 + s) * 16);
    }
#pragma unroll
    for (int s = 0; s < 4; s++) {
      uint32_t off = row * 128 + (sg0 + s) * 16;
      uint32_t sw = off ^ ((off >> 3) & 0x70);
      *(uint4*)(smem + (Abase - sb) + sw) = av[s];
      *(uint4*)(smem + (Bbase - sb) + sw) = bv[s];
    }
    __syncthreads();
    if (wid == 0) {
      if (elect_one()) {
        fence_async_shared();
        uint64_t ad = smem_desc_sw128(Abase);
        uint64_t bd = smem_desc_sw128(Bbase);
#pragma unroll
        for (int k = 0; k < 4; k++)
          mma_f16_ss(tmem, ad + k * 2, bd + k * 2, IDESC, (t > 0 || k > 0) ? 1u : 0u);
        tcommit(p == 0 ? MBAR0 : MBAR1);
      }
    }
  }
  mbar_wait(MBAR1, ph1);
  tfence_after();

  if (wid < 4) {
    const int lid = tid & 31;
    const int orow = m0 + wid * 32 + lid;
#pragma unroll
    for (int cb = 0; cb < 128; cb += 32) {
      uint32_t d[32];
      TC_LD_X32(d, tmem + cb);
      tc_wait_ld();
      float* dst = g_qkv + (size_t)orow * QKV_N + n0 + cb;
#pragma unroll
      for (int c = 0; c < 32; c += 4)
        *(float4*)(dst + c) = make_float4(__uint_as_float(d[c]),
                                          __uint_as_float(d[c + 1]),
                                          __uint_as_float(d[c + 2]),
                                          __uint_as_float(d[c + 3]));
    }
  }
  __syncthreads();
  if (wid == 0) tmem_dealloc(tmem, 128);

#else  // ------------- FFMA fallback (non-sm_103a pass; still correct) -------
  extern __shared__ char smemraw[];
  float* sA = (float*)smemraw;
  float* sB = sA + 16 * 128;
  const int K = DM, N = QKV_N;
  const int tid = threadIdx.x;
  const int tx = tid & 15, ty = tid >> 4;
  const int row0 = blockIdx.y * 128;
  const int col0 = blockIdx.x * 128;

  float acc[8][8];
#pragma unroll
  for (int r = 0; r < 8; r++)
#pragma unroll
    for (int c = 0; c < 8; c++) acc[r][c] = 0.f;

  for (int kk = 0; kk < K; kk += 16) {
#pragma unroll
    for (int it = 0; it < 2; it++) {
      int e = tid + it * 256;
      int ar = e >> 2;
      int ac = (e & 3) * 4;
      float4 a4 = *(const float4*)(X + (size_t)(row0 + ar) * K + kk + ac);
      sA[(ac + 0) * 128 + ar] = a4.x;
      sA[(ac + 1) * 128 + ar] = a4.y;
      sA[(ac + 2) * 128 + ar] = a4.z;
      sA[(ac + 3) * 128 + ar] = a4.w;
    }
#pragma unroll
    for (int it = 0; it < 2; it++) {
      int e = tid + it * 256;
      int br = e >> 5;
      int bc = (e & 31) * 4;
      *(float4*)&sB[br * 128 + bc] = *(const float4*)(W + (size_t)(kk + br) * N + col0 + bc);
    }
    __syncthreads();
#pragma unroll
    for (int k = 0; k < 16; k++) {
      float ar[8], bc[8];
      *(float4*)&ar[0] = *(float4*)&sA[k * 128 + ty * 8];
      *(float4*)&ar[4] = *(float4*)&sA[k * 128 + ty * 8 + 4];
      *(float4*)&bc[0] = *(float4*)&sB[k * 128 + tx * 8];
      *(float4*)&bc[4] = *(float4*)&sB[k * 128 + tx * 8 + 4];
#pragma unroll
      for (int r = 0; r < 8; r++)
#pragma unroll
        for (int c = 0; c < 8; c++) acc[r][c] += ar[r] * bc[c];
    }
    __syncthreads();
  }
#pragma unroll
  for (int r = 0; r < 8; r++) {
    float* dst = g_qkv + (size_t)(row0 + ty * 8 + r) * QKV_N + col0 + tx * 8;
    *(float4*)dst       = make_float4(acc[r][0], acc[r][1], acc[r][2], acc[r][3]);
    *(float4*)(dst + 4) = make_float4(acc[r][4], acc[r][5], acc[r][6], acc[r][7]);
  }
#endif
}

// ===========================================================================
// Kernel: fused score. 64x64 tile, 256 threads, BLOCKED 4x4 per thread with
// vectorized LDS.128. attn_score = (AC + BD + E)/8 + prev -> prev_out
// ===========================================================================
namespace {
constexpr int SC_SMEM = (4096 + 4096 + 8192 + 8192) * 4;  // 98304 B
}

__global__ __launch_bounds__(256) void k_score(const float* __restrict__ rrb,
                                               const float* __restrict__ rwb,
                                               const float* __restrict__ relpos,
                                               const float* __restrict__ prev,
                                               const int* __restrict__ skip,
                                               float* __restrict__ prev_out) {
  extern __shared__ float smemf[];
  float* sQT = smemf;             // [64][64]  d-major
  float* sKT = sQT + 4096;        // [64][64]
  float* sRq = sKT + 4096;        // [64][128] band for BD (127 used)
  float* sRe = sRq + 8192;        // [64][128] band for E
  __shared__ float cK[64];        // rrb . k_j
  __shared__ float cRq[128];      // rwb . R_t (127 used)

  const int bh = blockIdx.z;
  const int b = bh >> 4, h = bh & 15;
  const int tid = threadIdx.x;
  const int tx = tid & 15, ty = tid >> 4;
  const int i0 = blockIdx.y * 64;
  const int j0 = blockIdx.x * 64;

  const float* Qb = g_qkv + (size_t)(b * SEQ) * QKV_N + h * HD;
  const float* Kb = Qb + DM;

  // load q/k tiles transposed into smem (d-major)
#pragma unroll
  for (int it = 0; it < 4; it++) {
    int e = tid + it * 256;       // 64 rows x 16 float4
    int r = e >> 4;
    int c = (e & 15) * 4;
    float4 q4 = *(const float4*)(Qb + (size_t)(i0 + r) * QKV_N + c);
    sQT[(c + 0) * 64 + r] = q4.x;
    sQT[(c + 1) * 64 + r] = q4.y;
    sQT[(c + 2) * 64 + r] = q4.z;
    sQT[(c + 3) * 64 + r] = q4.w;
    float4 k4 = *(const float4*)(Kb + (size_t)(j0 + r) * QKV_N + c);
    sKT[(c + 0) * 64 + r] = k4.x;
    sKT[(c + 1) * 64 + r] = k4.y;
    sKT[(c + 2) * 64 + r] = k4.z;
    sKT[(c + 3) * 64 + r] = k4.w;
  }
  // R bands: global cols [q0, q0+126] and [u0, u0+126]; always within [1,1023]
  {
    const int q0 = SEQ + (j0 - i0) - 63;
    const int u0 = SEQ + (i0 - j0) - 63;
    for (int e = tid; e < 64 * 127; e += 256) {
      int d = e / 127, x = e - d * 127;
      sRq[d * 128 + x] = relpos[(size_t)d * P2 + q0 + x];
      sRe[d * 128 + x] = relpos[(size_t)d * P2 + u0 + x];
    }
  }
  __syncthreads();

  // rank-1 bias corrections
  if (tid < 64) {
    float s = 0.f;
#pragma unroll
    for (int d = 0; d < 64; d++) s += rrb[h * HD + d] * sKT[d * 64 + tid];
    cK[tid] = s;
  } else if (tid < 64 + 127) {
    int t = tid - 64;
    float s = 0.f;
#pragma unroll
    for (int d = 0; d < 64; d++) s += rwb[h * HD + d] * sRq[d * 128 + t];
    cRq[t] = s;
  }
  __syncthreads();

  float acc[4][4];
#pragma unroll
  for (int r = 0; r < 4; r++)
#pragma unroll
    for (int c = 0; c < 4; c++) acc[r][c] = 0.f;

  // blocked tile: rows i0 + ty*4 + r, cols j0 + tx*4 + c
  // band local idx = (4tx + c) - (4ty + r) + 63 = rqb + (c - r + 3)
  const int rqb = 4 * (tx - ty) + 60;   // 16B-aligned, in [0, 120]
  const int reb = 4 * (ty - tx) + 60;

#pragma unroll 8
  for (int d = 0; d < 64; d++) {
    float4 a4  = *(float4*)&sQT[d * 64 + ty * 4];
    float4 b4  = *(float4*)&sKT[d * 64 + tx * 4];
    float4 q0v = *(float4*)&sRq[d * 128 + rqb];
    float4 q1v = *(float4*)&sRq[d * 128 + rqb + 4];
    float4 e0v = *(float4*)&sRe[d * 128 + reb];
    float4 e1v = *(float4*)&sRe[d * 128 + reb + 4];
    float a[4]  = {a4.x, a4.y, a4.z, a4.w};
    float bb[4] = {b4.x, b4.y, b4.z, b4.w};
    float rq[8] = {q0v.x, q0v.y, q0v.z, q0v.w, q1v.x, q1v.y, q1v.z, q1v.w};
    float re[8] = {e0v.x, e0v.y, e0v.z, e0v.w, e1v.x, e1v.y, e1v.z, e1v.w};
#pragma unroll
    for (int r = 0; r < 4; r++)
#pragma unroll
      for (int c = 0; c < 4; c++)
        acc[r][c] += a[r] * bb[c] + a[r] * rq[c - r + 3] + bb[c] * re[r - c + 3];
  }

  const int sk = *skip;
  const float* prevb = prev + (size_t)bh * SEQ * SEQ;
  float* outb = prev_out + (size_t)bh * SEQ * SEQ;

#pragma unroll
  for (int r = 0; r < 4; r++) {
    const int i = i0 + ty * 4 + r;
    const int j = j0 + tx * 4;
    float4 p = make_float4(0.f, 0.f, 0.f, 0.f);
    if (sk) p = *(const float4*)(prevb + (size_t)i * SEQ + j);
    float4 o;
    o.x = (acc[r][0] + cK[tx * 4 + 0] + cRq[rqb + 0 - r + 3]) * 0.125f + p.x;
    o.y = (acc[r][1] + cK[tx * 4 + 1] + cRq[rqb + 1 - r + 3]) * 0.125f + p.y;
    o.z = (acc[r][2] + cK[tx * 4 + 2] + cRq[rqb + 2 - r + 3]) * 0.125f + p.z;
    o.w = (acc[r][3] + cK[tx * 4 + 3] + cRq[rqb + 3 - r + 3]) * 0.125f + p.w;
    *(float4*)(outb + (size_t)i * SEQ + j) = o;
  }
}

// ===========================================================================
// Kernel: out = softmax(S) @ V (reverted to round-7 form)
// ===========================================================================
namespace {
constexpr int ROWS_AV   = 64;
constexpr int SS_STRIDE = 516;
constexpr int SMEM_AV   = (ROWS_AV * SS_STRIDE + 64 * 64) * 4;  // 148480 B
}

__global__ __launch_bounds__(256) void k_av(const float* __restrict__ Sglob,
                                            float* __restrict__ Out) {
  extern __shared__ float smemf[];
  float* sS = smemf;
  float* sV = smemf + ROWS_AV * SS_STRIDE;
  __shared__ float sSum[ROWS_AV];

  const int bh = blockIdx.y;
  const int b = bh >> 4, h = bh & 15;
  const int row0 = blockIdx.x * ROWS_AV;
  const int tid = threadIdx.x;
  const int tx = tid & 15, ty = tid >> 4;
  const float* Sb = Sglob + ((size_t)bh * SEQ + row0) * SEQ;

#pragma unroll
  for (int it = 0; it < 32; it++) {
    int e = tid + it * 256;
    int r = e >> 7;
    int c = (e & 127) * 4;
    *(float4*)&sS[r * SS_STRIDE + c] = *(const float4*)(Sb + (size_t)r * SEQ + c);
  }
  __syncthreads();

  {
    const int warp = tid >> 5, lane = tid & 31;
#pragma unroll
    for (int rr = 0; rr < 8; rr++) {
      int row = warp * 8 + rr;
      float* srow = sS + row * SS_STRIDE;
      float mx = -1e30f;
      for (int c = lane; c < SEQ; c += 32) mx = fmaxf(mx, srow[c]);
#pragma unroll
      for (int o = 16; o > 0; o >>= 1) mx = fmaxf(mx, __shfl_xor_sync(0xffffffffu, mx, o));
      float sum = 0.f;
      for (int c = lane; c < SEQ; c += 32) {
        float p = __expf(srow[c] - mx);
        srow[c] = p;
        sum += p;
      }
#pragma unroll
      for (int o = 16; o > 0; o >>= 1) sum += __shfl_xor_sync(0xffffffffu, sum, o);
      if (lane == 0) sSum[row] = sum;
    }
  }

  float acc[4][4];
#pragma unroll
  for (int r = 0; r < 4; r++)
#pragma unroll
    for (int c = 0; c < 4; c++) acc[r][c] = 0.f;

  const float* Vb = g_qkv + (size_t)(b * SEQ) * QKV_N + 2 * DM + h * HD;
  for (int kc = 0; kc < SEQ; kc += 64) {
    __syncthreads();
#pragma unroll
    for (int it = 0; it < 4; it++) {
      int e = tid + it * 256;
      int kk = e >> 4;
      int c = (e & 15) * 4;
      *(float4*)&sV[kk * 64 + c] = *(const float4*)(Vb + (size_t)(kc + kk) * QKV_N + c);
    }
    __syncthreads();
#pragma unroll 8
    for (int kk = 0; kk < 64; kk++) {
      float p[4], v[4];
#pragma unroll
      for (int r = 0; r < 4; r++) p[r] = sS[(ty + 16 * r) * SS_STRIDE + kc + kk];
#pragma unroll
      for (int c = 0; c < 4; c++) v[c] = sV[kk * 64 + tx + 16 * c];
#pragma unroll
      for (int r = 0; r < 4; r++)
#pragma unroll
        for (int c = 0; c < 4; c++) acc[r][c] += p[r] * v[c];
    }
  }

#pragma unroll
  for (int r = 0; r < 4; r++) {
    const float inv = 1.f / sSum[ty + 16 * r];
    float* dst = Out + ((size_t)b * SEQ + row0 + ty + 16 * r) * DM + h * HD + tx;
#pragma unroll
    for (int c = 0; c < 4; c++) dst[16 * c] = acc[r][c] * inv;
  }
}

// ---------------------------------------------------------------------------
extern "C" void kernel_launch(void* const* d_in, const int* in_sizes, int n_in,
                              void* d_out, int out_size) {
  const float* x      = (const float*)d_in[0];
  const float* prev   = (const float*)d_in[1];
  const float* Wqkv   = (const float*)d_in[2];
  const float* rrb    = (const float*)d_in[3];
  const float* rwb    = (const float*)d_in[4];
  const float* relpos = (const float*)d_in[5];
  const int*   skip   = (const int*)d_in[6];

  float* out      = (float*)d_out;                       // (8,512,1024)
  float* prev_out = out + (size_t)BATCH * SEQ * DM;      // (8,16,512,512)

  k_convA<<<(MROWS * DM / 4) / 256, 256>>>(x);
  k_convB<<<dim3(QKV_N / 32, DM / 32), 256>>>(Wqkv);

  cudaFuncSetAttribute(k_qkv_mma, cudaFuncAttributeMaxDynamicSharedMemorySize, QSMEM);
  k_qkv_mma<<<dim3(QKV_N / 128, MROWS / 128), 256, QSMEM>>>(x, Wqkv);

  cudaFuncSetAttribute(k_score, cudaFuncAttributeMaxDynamicSharedMemorySize, SC_SMEM);
  dim3 g3(SEQ / 64, SEQ / 64, BH);                       // (8, 8, 128)
  k_score<<<g3, 256, SC_SMEM>>>(rrb, rwb, relpos, prev, skip, prev_out);

  cudaFuncSetAttribute(k_av, cudaFuncAttributeMaxDynamicSharedMemorySize, SMEM_AV);
  dim3 g4(SEQ / ROWS_AV, BH);                            // (8, 128)
  k_av<<<g4, 256, SMEM_AV>>>(prev_out, out);
}

// round 10
// speedup vs baseline: 1.6244x; 1.0419x over previous
#include <cuda_runtime.h>
#include <cuda_bf16.h>
#include <cstdint>

// ---------------------------------------------------------------------------
// RelativeMultiHeadAttn (Transformer-XL style) forward.
//
// qkv = x @ Wqkv via tcgen05 bf16 split-precision GEMM (K concat trick):
//   A2 = [Xhi | Xlo | Xhi]  (4096 x 3072 bf16, K-major)
//   B2 = [Whi | Whi | Wlo]^T (3072 x 3072 bf16, K-major)
//   qkv = A2 @ B2^T  accumulated fp32 in TMEM  ==  x@W up to ~2^-18 residual.
// tcgen05 / f32x2 bodies guarded for the sm_103a arch-specific pass; the
// plain compute_103 pass compiles scalar fp32 fallbacks.
//
// score: 64x64 tiles, blocked 4x4/thread with LDS.128, d-chunked R bands
// (48KB smem -> 4 CTAs/SM); band-product trick:
//   BD_shift[i,j] = (q_i + r_w) . R[:, L + j - i]
//   E_term[i,j]   = k_j . R[:, L + i - j]
// av: softmax + PV with packed f32x2 FMAs over d-pairs.
// ---------------------------------------------------------------------------

namespace {
constexpr int BATCH = 8;
constexpr int NH    = 16;
constexpr int SEQ   = 512;
constexpr int DM    = 1024;
constexpr int HD    = 64;
constexpr int P2    = 2 * SEQ;      // 1024
constexpr int BH    = BATCH * NH;   // 128
constexpr int QKV_N = 3 * DM;       // 3072
constexpr int MROWS = BATCH * SEQ;  // 4096
constexpr int KTOT  = 3 * DM;       // 3072 (split-K concat)
constexpr int CH    = 64;           // K chunk (one SW128 atom column of bf16)
constexpr int NCH   = KTOT / CH;    // 48
}

// scratch (static device globals: allowed; no dynamic allocation)
__device__ float         g_qkv[(size_t)MROWS * QKV_N];    // 50 MB fp32
__device__ __nv_bfloat16 g_A2[(size_t)MROWS * KTOT];      // 25 MB
__device__ __nv_bfloat16 g_B2[(size_t)QKV_N * KTOT];      // 19 MB

// Feature gate: true only in the sm_103a (arch-specific) device pass.
#ifndef __CUDA_ARCH_SPECIFIC__
#define __CUDA_ARCH_SPECIFIC__ 0
#endif
#if !defined(__CUDA_ARCH__) || defined(__CUDA_ARCH_FEAT_SM103_ALL) || \
    (__CUDA_ARCH_SPECIFIC__ == 1030)
#define HAS_TCGEN05 1
#else
#define HAS_TCGEN05 0
#endif

// ===========================================================================
// minimal sm_103a PTX helpers
// ===========================================================================
__device__ __forceinline__ uint32_t smem_u32(const void* p) {
  uint32_t a;
  asm("{ .reg .u64 t; cvta.to.shared.u64 t, %1; cvt.u32.u64 %0, t; }"
      : "=r"(a) : "l"(p));
  return a;
}
#if HAS_TCGEN05
__device__ __forceinline__ uint32_t elect_one() {
  uint32_t pred;
  asm volatile("{\n\t.reg .pred p;\n\telect.sync _|p, 0xFFFFFFFF;\n\t"
               "selp.b32 %0, 1, 0, p;\n\t}" : "=r"(pred));
  return pred;
}
__device__ __forceinline__ void mbar_init(uint32_t mbar, uint32_t cnt) {
  asm volatile("mbarrier.init.shared.b64 [%0], %1;" :: "r"(mbar), "r"(cnt) : "memory");
}
__device__ __forceinline__ void mbar_wait(uint32_t mbar, uint32_t parity) {
  asm volatile(
      "{\n\t.reg .pred P;\n\t"
      "WL_%=:\n\t"
      "mbarrier.try_wait.parity.acquire.cta.shared::cta.b64 P, [%0], %1, 0x989680;\n\t"
      "@P bra.uni WD_%=;\n\t"
      "bra.uni WL_%=;\n\t"
      "WD_%=:\n\t}"
      :: "r"(mbar), "r"(parity) : "memory");
}
__device__ __forceinline__ void tmem_alloc(uint32_t smem_dst, uint32_t ncols) {
  asm volatile("tcgen05.alloc.cta_group::1.sync.aligned.shared::cta.b32 [%0], %1;"
               :: "r"(smem_dst), "r"(ncols) : "memory");
}
__device__ __forceinline__ void tmem_relinq() {
  asm volatile("tcgen05.relinquish_alloc_permit.cta_group::1.sync.aligned;");
}
__device__ __forceinline__ void tmem_dealloc(uint32_t tmem, uint32_t ncols) {
  asm volatile("tcgen05.dealloc.cta_group::1.sync.aligned.b32 %0, %1;"
               :: "r"(tmem), "r"(ncols));
}
__device__ __forceinline__ void tcommit(uint32_t mbar) {
  asm volatile(
      "tcgen05.commit.cta_group::1.mbarrier::arrive::one.shared::cluster.b64 [%0];"
      :: "r"(mbar) : "memory");
}
__device__ __forceinline__ void fence_async_shared() {
  asm volatile("fence.proxy.async.shared::cta;" ::: "memory");
}
__device__ __forceinline__ void tfence_after() {
  asm volatile("tcgen05.fence::after_thread_sync;" ::: "memory");
}
__device__ __forceinline__ void mma_f16_ss(uint32_t d, uint64_t ad, uint64_t bd,
                                           uint32_t idesc, uint32_t en) {
  asm volatile(
      "{\n\t.reg .pred p;\n\tsetp.ne.u32 p, %5, 0;\n\t"
      "tcgen05.mma.cta_group::1.kind::f16 [%0], %1, %2, %3, {%4, %4, %4, %4}, p;\n\t}"
      :: "r"(d), "l"(ad), "l"(bd), "r"(idesc), "r"(0u), "r"(en) : "memory");
}
#define TC_LD_X32(r, addr)                                                      \
  asm volatile(                                                                 \
      "tcgen05.ld.sync.aligned.32x32b.x32.b32 "                                 \
      "{%0,%1,%2,%3,%4,%5,%6,%7,%8,%9,%10,%11,%12,%13,%14,%15,"                \
      "%16,%17,%18,%19,%20,%21,%22,%23,%24,%25,%26,%27,%28,%29,%30,%31}, [%32];" \
      : "=r"((r)[0]), "=r"((r)[1]), "=r"((r)[2]), "=r"((r)[3]),                 \
        "=r"((r)[4]), "=r"((r)[5]), "=r"((r)[6]), "=r"((r)[7]),                 \
        "=r"((r)[8]), "=r"((r)[9]), "=r"((r)[10]), "=r"((r)[11]),               \
        "=r"((r)[12]), "=r"((r)[13]), "=r"((r)[14]), "=r"((r)[15]),             \
        "=r"((r)[16]), "=r"((r)[17]), "=r"((r)[18]), "=r"((r)[19]),             \
        "=r"((r)[20]), "=r"((r)[21]), "=r"((r)[22]), "=r"((r)[23]),             \
        "=r"((r)[24]), "=r"((r)[25]), "=r"((r)[26]), "=r"((r)[27]),             \
        "=r"((r)[28]), "=r"((r)[29]), "=r"((r)[30]), "=r"((r)[31])              \
      : "r"(addr))
__device__ __forceinline__ void tc_wait_ld() {
  asm volatile("tcgen05.wait::ld.sync.aligned;" ::: "memory");
}
// SW128 K-major SMEM descriptor (LBO=1, SBO=64, version=1, layout=2)
__device__ __forceinline__ uint64_t smem_desc_sw128(uint32_t addr) {
  const uint64_t base = (uint64_t(2) << 61) | (uint64_t(1) << 46) |
                        (uint64_t(64) << 32) | (uint64_t(1) << 16);
  return base | ((uint64_t)(addr >> 4) & 0x3FFF);
}
// packed fp32x2 FMA: d.lo += a.lo*b.lo ; d.hi += a.hi*b.hi
__device__ __forceinline__ void ffma2(unsigned long long& d,
                                      unsigned long long a,
                                      unsigned long long b) {
  asm("fma.rn.f32x2 %0, %1, %2, %0;" : "+l"(d) : "l"(a), "l"(b));
}
#endif  // HAS_TCGEN05

// idesc: fp32 accum, bf16 x bf16, M=128, N=128
namespace {
constexpr uint32_t IDESC =
    (1u << 4) | (1u << 7) | (1u << 10) | ((128u / 8) << 17) | ((128u / 16) << 24);
}

// ===========================================================================
// Conversion kernels: fp32 -> split bf16 (hi/lo), B transposed to K-major
// ===========================================================================
__global__ __launch_bounds__(256) void k_convA(const float* __restrict__ X) {
  size_t i = (size_t)blockIdx.x * 256 + threadIdx.x;  // quad index
  float4 v = ((const float4*)X)[i];
  size_t m = i >> 8;
  size_t q = (i & 255) * 4;

  __nv_bfloat162 h01 = __floats2bfloat162_rn(v.x, v.y);
  __nv_bfloat162 h23 = __floats2bfloat162_rn(v.z, v.w);
  float lx = v.x - __bfloat162float(h01.x);
  float ly = v.y - __bfloat162float(h01.y);
  float lz = v.z - __bfloat162float(h23.x);
  float lw = v.w - __bfloat162float(h23.y);
  __nv_bfloat162 l01 = __floats2bfloat162_rn(lx, ly);
  __nv_bfloat162 l23 = __floats2bfloat162_rn(lz, lw);

  uint2 uh, ul;
  uh.x = *(uint32_t*)&h01; uh.y = *(uint32_t*)&h23;
  ul.x = *(uint32_t*)&l01; ul.y = *(uint32_t*)&l23;

  __nv_bfloat16* row = g_A2 + m * KTOT;
  *(uint2*)(row + q)          = uh;
  *(uint2*)(row + DM + q)     = ul;
  *(uint2*)(row + 2 * DM + q) = uh;
}

__global__ __launch_bounds__(256) void k_convB(const float* __restrict__ W) {
  __shared__ float tile[32][33];
  const int n0 = blockIdx.x * 32;
  const int k0 = blockIdx.y * 32;
  const int tid = threadIdx.x;
#pragma unroll
  for (int it = 0; it < 4; it++) {
    int e = tid + it * 256;
    int kk = e >> 5, nn = e & 31;
    tile[kk][nn] = W[(size_t)(k0 + kk) * QKV_N + n0 + nn];
  }
  __syncthreads();
#pragma unroll
  for (int it = 0; it < 4; it++) {
    int e = tid + it * 256;
    int nn = e >> 5, kk = e & 31;
    float x = tile[kk][nn];
    __nv_bfloat16 hi = __float2bfloat16_rn(x);
    __nv_bfloat16 lo = __float2bfloat16_rn(x - __bfloat162float(hi));
    __nv_bfloat16* row = g_B2 + (size_t)(n0 + nn) * KTOT;
    row[k0 + kk]          = hi;
    row[DM + k0 + kk]     = hi;
    row[2 * DM + k0 + kk] = lo;
  }
}

// ===========================================================================
// Kernel: qkv = A2 @ B2^T via tcgen05 (unchanged from round 7)
// ===========================================================================
namespace {
constexpr int QSMEM = 1024 + 4 * 16384;
}

__global__ __launch_bounds__(256) void k_qkv_mma(const float* __restrict__ X,
                                                 const float* __restrict__ W) {
#if HAS_TCGEN05
  extern __shared__ char smem[];
  const uint32_t sb = smem_u32(smem);
  const uint32_t TPTR  = sb;
  const uint32_t MBAR0 = sb + 16;
  const uint32_t MBAR1 = sb + 24;
  const uint32_t STAGE = sb + 1024;

  const int tid = threadIdx.x;
  const int wid = tid >> 5;

  if (wid == 0) tmem_alloc(TPTR, 128);
  if (tid == 0) { mbar_init(MBAR0, 1); mbar_init(MBAR1, 1); }
  __syncthreads();
  uint32_t tmem;
  asm volatile("ld.shared.b32 %0, [%1];" : "=r"(tmem) : "r"(TPTR));
  if (wid == 0) tmem_relinq();

  const int m0 = blockIdx.y * 128;
  const int n0 = blockIdx.x * 128;
  const __nv_bfloat16* Ag = g_A2 + (size_t)m0 * KTOT;
  const __nv_bfloat16* Bg = g_B2 + (size_t)n0 * KTOT;

  const int row = tid >> 1;
  const int sg0 = (tid & 1) * 4;

  uint32_t ph0 = 0, ph1 = 0;
  for (int t = 0; t < NCH; t++) {
    const int p = t & 1;
    const uint32_t Abase = STAGE + p * 32768;
    const uint32_t Bbase = Abase + 16384;
    if (t >= 2) {
      if (p == 0) { mbar_wait(MBAR0, ph0); ph0 ^= 1; }
      else        { mbar_wait(MBAR1, ph1); ph1 ^= 1; }
    }
    const int kc = t * CH;
    uint4 av[4], bv[4];
    const char* arow = (const char*)(Ag + (size_t)row * KTOT + kc);
    const char* brow = (const char*)(Bg + (size_t)row * KTOT + kc);
#pragma unroll
    for (int s = 0; s < 4; s++) {
      av[s] = *(const uint4*)(arow + (sg0 + s) * 16);
      bv[s] = *(const uint4*)(brow + (sg0 + s) * 16);
    }
#pragma unroll
    for (int s = 0; s < 4; s++) {
      uint32_t off = row * 128 + (sg0 + s) * 16;
      uint32_t sw = off ^ ((off >> 3) & 0x70);
      *(uint4*)(smem + (Abase - sb) + sw) = av[s];
      *(uint4*)(smem + (Bbase - sb) + sw) = bv[s];
    }
    __syncthreads();
    if (wid == 0) {
      if (elect_one()) {
        fence_async_shared();
        uint64_t ad = smem_desc_sw128(Abase);
        uint64_t bd = smem_desc_sw128(Bbase);
#pragma unroll
        for (int k = 0; k < 4; k++)
          mma_f16_ss(tmem, ad + k * 2, bd + k * 2, IDESC, (t > 0 || k > 0) ? 1u : 0u);
        tcommit(p == 0 ? MBAR0 : MBAR1);
      }
    }
  }
  mbar_wait(MBAR1, ph1);
  tfence_after();

  if (wid < 4) {
    const int lid = tid & 31;
    const int orow = m0 + wid * 32 + lid;
#pragma unroll
    for (int cb = 0; cb < 128; cb += 32) {
      uint32_t d[32];
      TC_LD_X32(d, tmem + cb);
      tc_wait_ld();
      float* dst = g_qkv + (size_t)orow * QKV_N + n0 + cb;
#pragma unroll
      for (int c = 0; c < 32; c += 4)
        *(float4*)(dst + c) = make_float4(__uint_as_float(d[c]),
                                          __uint_as_float(d[c + 1]),
                                          __uint_as_float(d[c + 2]),
                                          __uint_as_float(d[c + 3]));
    }
  }
  __syncthreads();
  if (wid == 0) tmem_dealloc(tmem, 128);

#else  // ------------- FFMA fallback (non-sm_103a pass; still correct) -------
  extern __shared__ char smemraw[];
  float* sA = (float*)smemraw;
  float* sB = sA + 16 * 128;
  const int K = DM, N = QKV_N;
  const int tid = threadIdx.x;
  const int tx = tid & 15, ty = tid >> 4;
  const int row0 = blockIdx.y * 128;
  const int col0 = blockIdx.x * 128;

  float acc[8][8];
#pragma unroll
  for (int r = 0; r < 8; r++)
#pragma unroll
    for (int c = 0; c < 8; c++) acc[r][c] = 0.f;

  for (int kk = 0; kk < K; kk += 16) {
#pragma unroll
    for (int it = 0; it < 2; it++) {
      int e = tid + it * 256;
      int ar = e >> 2;
      int ac = (e & 3) * 4;
      float4 a4 = *(const float4*)(X + (size_t)(row0 + ar) * K + kk + ac);
      sA[(ac + 0) * 128 + ar] = a4.x;
      sA[(ac + 1) * 128 + ar] = a4.y;
      sA[(ac + 2) * 128 + ar] = a4.z;
      sA[(ac + 3) * 128 + ar] = a4.w;
    }
#pragma unroll
    for (int it = 0; it < 2; it++) {
      int e = tid + it * 256;
      int br = e >> 5;
      int bc = (e & 31) * 4;
      *(float4*)&sB[br * 128 + bc] = *(const float4*)(W + (size_t)(kk + br) * N + col0 + bc);
    }
    __syncthreads();
#pragma unroll
    for (int k = 0; k < 16; k++) {
      float ar[8], bc[8];
      *(float4*)&ar[0] = *(float4*)&sA[k * 128 + ty * 8];
      *(float4*)&ar[4] = *(float4*)&sA[k * 128 + ty * 8 + 4];
      *(float4*)&bc[0] = *(float4*)&sB[k * 128 + tx * 8];
      *(float4*)&bc[4] = *(float4*)&sB[k * 128 + tx * 8 + 4];
#pragma unroll
      for (int r = 0; r < 8; r++)
#pragma unroll
        for (int c = 0; c < 8; c++) acc[r][c] += ar[r] * bc[c];
    }
    __syncthreads();
  }
#pragma unroll
  for (int r = 0; r < 8; r++) {
    float* dst = g_qkv + (size_t)(row0 + ty * 8 + r) * QKV_N + col0 + tx * 8;
    *(float4*)dst       = make_float4(acc[r][0], acc[r][1], acc[r][2], acc[r][3]);
    *(float4*)(dst + 4) = make_float4(acc[r][4], acc[r][5], acc[r][6], acc[r][7]);
  }
#endif
}

// ===========================================================================
// Kernel: fused score. 64x64 tile, 256 threads, blocked 4x4 with LDS.128.
// R bands d-chunked (DCH=16) -> 48KB smem -> 4 CTAs/SM.
// attn_score = (AC + BD + E)/8 + prev -> prev_out
// ===========================================================================
namespace {
constexpr int DCH     = 16;
constexpr int SC_SMEM = (4096 + 4096 + DCH * 128 + DCH * 128) * 4;  // 49152 B
}

__global__ __launch_bounds__(256, 4) void k_score(const float* __restrict__ rrb,
                                                  const float* __restrict__ rwb,
                                                  const float* __restrict__ relpos,
                                                  const float* __restrict__ prev,
                                                  const int* __restrict__ skip,
                                                  float* __restrict__ prev_out) {
  extern __shared__ float smemf[];
  float* sQT = smemf;             // [64 d][64 r]
  float* sKT = sQT + 4096;        // [64 d][64 c]
  float* sRq = sKT + 4096;        // [DCH][128] band chunk for BD (127 used)
  float* sRe = sRq + DCH * 128;   // [DCH][128] band chunk for E
  __shared__ float cK[64];        // rrb . k_j
  __shared__ float cRq[128];      // rwb . R_t (127 used), accumulated per chunk

  const int bh = blockIdx.z;
  const int b = bh >> 4, h = bh & 15;
  const int tid = threadIdx.x;
  const int tx = tid & 15, ty = tid >> 4;
  const int i0 = blockIdx.y * 64;
  const int j0 = blockIdx.x * 64;

  const float* Qb = g_qkv + (size_t)(b * SEQ) * QKV_N + h * HD;
  const float* Kb = Qb + DM;

  // load q/k tiles transposed into smem (d-major)
#pragma unroll
  for (int it = 0; it < 4; it++) {
    int e = tid + it * 256;       // 64 rows x 16 float4
    int r = e >> 4;
    int c = (e & 15) * 4;
    float4 q4 = *(const float4*)(Qb + (size_t)(i0 + r) * QKV_N + c);
    sQT[(c + 0) * 64 + r] = q4.x;
    sQT[(c + 1) * 64 + r] = q4.y;
    sQT[(c + 2) * 64 + r] = q4.z;
    sQT[(c + 3) * 64 + r] = q4.w;
    float4 k4 = *(const float4*)(Kb + (size_t)(j0 + r) * QKV_N + c);
    sKT[(c + 0) * 64 + r] = k4.x;
    sKT[(c + 1) * 64 + r] = k4.y;
    sKT[(c + 2) * 64 + r] = k4.z;
    sKT[(c + 3) * 64 + r] = k4.w;
  }
  if (tid < 128) cRq[tid] = 0.f;
  __syncthreads();

  // rank-1 correction cK (needs full-K sKT, available now)
  if (tid < 64) {
    float s = 0.f;
#pragma unroll
    for (int d = 0; d < 64; d++) s += rrb[h * HD + d] * sKT[d * 64 + tid];
    cK[tid] = s;
  }

  float acc[4][4];
#pragma unroll
  for (int r = 0; r < 4; r++)
#pragma unroll
    for (int c = 0; c < 4; c++) acc[r][c] = 0.f;

  // blocked tile: rows i0 + ty*4 + r, cols j0 + tx*4 + c
  const int rqb = 4 * (tx - ty) + 60;   // 16B-aligned, in [0, 120]
  const int reb = 4 * (ty - tx) + 60;
  const int q0 = SEQ + (j0 - i0) - 63;  // band starts, always within [1,1023]
  const int u0 = SEQ + (i0 - j0) - 63;

  for (int chk = 0; chk < 64 / DCH; chk++) {
    const int d0 = chk * DCH;
    // fill band chunk (prev chunk consumers done: sync at loop end / above)
    for (int e = tid; e < DCH * 128; e += 256) {
      int dl = e >> 7, x = e & 127;
      if (x < 127) {
        sRq[dl * 128 + x] = relpos[(size_t)(d0 + dl) * P2 + q0 + x];
        sRe[dl * 128 + x] = relpos[(size_t)(d0 + dl) * P2 + u0 + x];
      }
    }
    __syncthreads();

    // accumulate cRq partial for this chunk
    if (tid < 127) {
      float s = 0.f;
#pragma unroll
      for (int dl = 0; dl < DCH; dl++)
        s += rwb[h * HD + d0 + dl] * sRq[dl * 128 + tid];
      cRq[tid] += s;
    }

#pragma unroll
    for (int dl = 0; dl < DCH; dl++) {
      const int d = d0 + dl;
      float4 a4  = *(float4*)&sQT[d * 64 + ty * 4];
      float4 b4  = *(float4*)&sKT[d * 64 + tx * 4];
      float4 q0v = *(float4*)&sRq[dl * 128 + rqb];
      float4 q1v = *(float4*)&sRq[dl * 128 + rqb + 4];
      float4 e0v = *(float4*)&sRe[dl * 128 + reb];
      float4 e1v = *(float4*)&sRe[dl * 128 + reb + 4];
      float a[4]  = {a4.x, a4.y, a4.z, a4.w};
      float bb[4] = {b4.x, b4.y, b4.z, b4.w};
      float rq[8] = {q0v.x, q0v.y, q0v.z, q0v.w, q1v.x, q1v.y, q1v.z, q1v.w};
      float re[8] = {e0v.x, e0v.y, e0v.z, e0v.w, e1v.x, e1v.y, e1v.z, e1v.w};
#pragma unroll
      for (int r = 0; r < 4; r++)
#pragma unroll
        for (int c = 0; c < 4; c++)
          acc[r][c] += a[r] * bb[c] + a[r] * rq[c - r + 3] + bb[c] * re[r - c + 3];
    }
    __syncthreads();
  }

  const int sk = *skip;
  const float* prevb = prev + (size_t)bh * SEQ * SEQ;
  float* outb = prev_out + (size_t)bh * SEQ * SEQ;

#pragma unroll
  for (int r = 0; r < 4; r++) {
    const int i = i0 + ty * 4 + r;
    const int j = j0 + tx * 4;
    float4 p = make_float4(0.f, 0.f, 0.f, 0.f);
    if (sk) p = *(const float4*)(prevb + (size_t)i * SEQ + j);
    float4 o;
    o.x = (acc[r][0] + cK[tx * 4 + 0] + cRq[rqb + 0 - r + 3]) * 0.125f + p.x;
    o.y = (acc[r][1] + cK[tx * 4 + 1] + cRq[rqb + 1 - r + 3]) * 0.125f + p.y;
    o.z = (acc[r][2] + cK[tx * 4 + 2] + cRq[rqb + 2 - r + 3]) * 0.125f + p.z;
    o.w = (acc[r][3] + cK[tx * 4 + 3] + cRq[rqb + 3 - r + 3]) * 0.125f + p.w;
    *(float4*)(outb + (size_t)i * SEQ + j) = o;
  }
}

// ===========================================================================
// Kernel: out = softmax(S) @ V. 64 rows/block, 4x4 tile.
// sm_103a path: packed f32x2 FMAs over d-pairs, V stored d-interleaved.
// ===========================================================================
namespace {
constexpr int ROWS_AV   = 64;
constexpr int SS_STRIDE = 516;
constexpr int SMEM_AV   = (ROWS_AV * SS_STRIDE + 64 * 64) * 4;  // 148480 B
}

__global__ __launch_bounds__(256) void k_av(const float* __restrict__ Sglob,
                                            float* __restrict__ Out) {
  extern __shared__ float smemf[];
  float* sS = smemf;
  float* sV = smemf + ROWS_AV * SS_STRIDE;   // f32x2 path: [32 kp][64 c][2]
  __shared__ float sSum[ROWS_AV];

  const int bh = blockIdx.y;
  const int b = bh >> 4, h = bh & 15;
  const int row0 = blockIdx.x * ROWS_AV;
  const int tid = threadIdx.x;
  const int tx = tid & 15, ty = tid >> 4;
  const float* Sb = Sglob + ((size_t)bh * SEQ + row0) * SEQ;

#pragma unroll
  for (int it = 0; it < 32; it++) {
    int e = tid + it * 256;
    int r = e >> 7;
    int c = (e & 127) * 4;
    *(float4*)&sS[r * SS_STRIDE + c] = *(const float4*)(Sb + (size_t)r * SEQ + c);
  }
  __syncthreads();

  {
    const int warp = tid >> 5, lane = tid & 31;
#pragma unroll
    for (int rr = 0; rr < 8; rr++) {
      int row = warp * 8 + rr;
      float* srow = sS + row * SS_STRIDE;
      float mx = -1e30f;
      for (int c = lane; c < SEQ; c += 32) mx = fmaxf(mx, srow[c]);
#pragma unroll
      for (int o = 16; o > 0; o >>= 1) mx = fmaxf(mx, __shfl_xor_sync(0xffffffffu, mx, o));
      float sum = 0.f;
      for (int c = lane; c < SEQ; c += 32) {
        float p = __expf(srow[c] - mx);
        srow[c] = p;
        sum += p;
      }
#pragma unroll
      for (int o = 16; o > 0; o >>= 1) sum += __shfl_xor_sync(0xffffffffu, sum, o);
      if (lane == 0) sSum[row] = sum;
    }
  }

  const float* Vb = g_qkv + (size_t)(b * SEQ) * QKV_N + 2 * DM + h * HD;

#if HAS_TCGEN05
  // ---- packed f32x2 PV: accumulate even-d in lane0, odd-d in lane1 ----
  unsigned long long acc2[4][4];
#pragma unroll
  for (int r = 0; r < 4; r++)
#pragma unroll
    for (int c = 0; c < 4; c++) acc2[r][c] = 0ull;

  for (int kc = 0; kc < SEQ; kc += 64) {
    __syncthreads();
    // fill V interleaved: sV[kp*128 + 2c + par] = V[kc + 2kp + par][c]
#pragma unroll
    for (int it = 0; it < 8; it++) {
      int e = tid + it * 256;     // 2048 tasks: kp = e>>6, c = e&63
      int kp = e >> 6;
      int c  = e & 63;
      float v0 = Vb[(size_t)(kc + 2 * kp) * QKV_N + c];
      float v1 = Vb[(size_t)(kc + 2 * kp + 1) * QKV_N + c];
      *(float2*)&sV[kp * 128 + 2 * c] = make_float2(v0, v1);
    }
    __syncthreads();
#pragma unroll 8
    for (int kp = 0; kp < 32; kp++) {
      unsigned long long p2[4], v2[4];
#pragma unroll
      for (int r = 0; r < 4; r++)
        p2[r] = *(const unsigned long long*)&sS[(ty + 16 * r) * SS_STRIDE + kc + 2 * kp];
#pragma unroll
      for (int c = 0; c < 4; c++)
        v2[c] = *(const unsigned long long*)&sV[kp * 128 + (tx + 16 * c) * 2];
#pragma unroll
      for (int r = 0; r < 4; r++)
#pragma unroll
        for (int c = 0; c < 4; c++) ffma2(acc2[r][c], p2[r], v2[c]);
    }
  }

#pragma unroll
  for (int r = 0; r < 4; r++) {
    const float inv = 1.f / sSum[ty + 16 * r];
    float* dst = Out + ((size_t)b * SEQ + row0 + ty + 16 * r) * DM + h * HD + tx;
#pragma unroll
    for (int c = 0; c < 4; c++) {
      float lo = __uint_as_float((uint32_t)(acc2[r][c] & 0xffffffffull));
      float hi = __uint_as_float((uint32_t)(acc2[r][c] >> 32));
      dst[16 * c] = (lo + hi) * inv;
    }
  }

#else
  // ---- scalar fallback (non-sm_103a pass) ----
  float acc[4][4];
#pragma unroll
  for (int r = 0; r < 4; r++)
#pragma unroll
    for (int c = 0; c < 4; c++) acc[r][c] = 0.f;

  for (int kc = 0; kc < SEQ; kc += 64) {
    __syncthreads();
#pragma unroll
    for (int it = 0; it < 4; it++) {
      int e = tid + it * 256;
      int kk = e >> 4;
      int c = (e & 15) * 4;
      *(float4*)&sV[kk * 64 + c] = *(const float4*)(Vb + (size_t)(kc + kk) * QKV_N + c);
    }
    __syncthreads();
#pragma unroll 8
    for (int kk = 0; kk < 64; kk++) {
      float p[4], v[4];
#pragma unroll
      for (int r = 0; r < 4; r++) p[r] = sS[(ty + 16 * r) * SS_STRIDE + kc + kk];
#pragma unroll
      for (int c = 0; c < 4; c++) v[c] = sV[kk * 64 + tx + 16 * c];
#pragma unroll
      for (int r = 0; r < 4; r++)
#pragma unroll
        for (int c = 0; c < 4; c++) acc[r][c] += p[r] * v[c];
    }
  }

#pragma unroll
  for (int r = 0; r < 4; r++) {
    const float inv = 1.f / sSum[ty + 16 * r];
    float* dst = Out + ((size_t)b * SEQ + row0 + ty + 16 * r) * DM + h * HD + tx;
#pragma unroll
    for (int c = 0; c < 4; c++) dst[16 * c] = acc[r][c] * inv;
  }
#endif
}

// ---------------------------------------------------------------------------
extern "C" void kernel_launch(void* const* d_in, const int* in_sizes, int n_in,
                              void* d_out, int out_size) {
  const float* x      = (const float*)d_in[0];
  const float* prev   = (const float*)d_in[1];
  const float* Wqkv   = (const float*)d_in[2];
  const float* rrb    = (const float*)d_in[3];
  const float* rwb    = (const float*)d_in[4];
  const float* relpos = (const float*)d_in[5];
  const int*   skip   = (const int*)d_in[6];

  float* out      = (float*)d_out;                       // (8,512,1024)
  float* prev_out = out + (size_t)BATCH * SEQ * DM;      // (8,16,512,512)

  k_convA<<<(MROWS * DM / 4) / 256, 256>>>(x);
  k_convB<<<dim3(QKV_N / 32, DM / 32), 256>>>(Wqkv);

  cudaFuncSetAttribute(k_qkv_mma, cudaFuncAttributeMaxDynamicSharedMemorySize, QSMEM);
  k_qkv_mma<<<dim3(QKV_N / 128, MROWS / 128), 256, QSMEM>>>(x, Wqkv);

  cudaFuncSetAttribute(k_score, cudaFuncAttributeMaxDynamicSharedMemorySize, SC_SMEM);
  dim3 g3(SEQ / 64, SEQ / 64, BH);                       // (8, 8, 128)
  k_score<<<g3, 256, SC_SMEM>>>(rrb, rwb, relpos, prev, skip, prev_out);

  cudaFuncSetAttribute(k_av, cudaFuncAttributeMaxDynamicSharedMemorySize, SMEM_AV);
  dim3 g4(SEQ / ROWS_AV, BH);                            // (8, 128)
  k_av<<<g4, 256, SMEM_AV>>>(prev_out, out);
}